// round 13
// baseline (speedup 1.0000x reference)
#include <cuda_runtime.h>
#include <cuda_bf16.h>
#include <cstdint>
#include <math.h>

// ===================== problem constants =====================
#define BB 4
#define TT 256
#define UU 128
#define ENC_H 512
#define PRED_H 640
#define JH 640
#define VC 1025            // real classes
#define VP 1152            // padded classes (9 * 128)
#define NCHUNK 9
#define NC 128             // classes per chunk
#define NSLICE 20          // K slices of 32 per chunk
#define NSL_TOT 180        // total K32 slices
#define NTHREADS 64
#define MROWS 32           // rows per CTA (quarter of a (b,t) tile)
#define WFRAG_U32 (90*16*2*32*4)   // 368640 uint32 = 1.47 MB

// ===================== device scratch ========================
__device__ float f_dev[BB*TT*JH];
__device__ float g_dev[BB*UU*JH];
__device__ uint32_t wfrag_dev[WFRAG_U32];   // W_joint in MMA-fragment order

// ===================== helpers ===========================
__device__ __forceinline__ uint32_t smem_to_u32(const void* p) {
    uint32_t a;
    asm("{ .reg .u64 t; cvta.to.shared.u64 t, %1; cvt.u32.u64 %0, t; }" : "=r"(a) : "l"(p));
    return a;
}
__device__ __forceinline__ uint32_t pack_bf16x2(float lo, float hi) {
    uint32_t p;
    asm("cvt.rn.bf16x2.f32 %0, %1, %2;" : "=r"(p) : "f"(hi), "f"(lo));
    return p;
}
__device__ __forceinline__ void ldsm_x4(uint32_t& r0, uint32_t& r1, uint32_t& r2, uint32_t& r3, uint32_t addr) {
    asm volatile("ldmatrix.sync.aligned.m8n8.x4.shared.b16 {%0,%1,%2,%3}, [%4];"
        : "=r"(r0), "=r"(r1), "=r"(r2), "=r"(r3) : "r"(addr));
}
__device__ __forceinline__ void mma16816(float* d, const uint32_t* a, uint32_t b0, uint32_t b1) {
    asm volatile("mma.sync.aligned.m16n8k16.row.col.f32.bf16.bf16.f32 "
        "{%0,%1,%2,%3}, {%4,%5,%6,%7}, {%8,%9}, {%0,%1,%2,%3};"
        : "+f"(d[0]), "+f"(d[1]), "+f"(d[2]), "+f"(d[3])
        : "r"(a[0]), "r"(a[1]), "r"(a[2]), "r"(a[3]), "r"(b0), "r"(b1));
}

// ===================== SMEM layout (relative to 1KB-aligned base) ==========
#define A_OFF      0                   // 32 x 640 bf16 swizzled: 40960 B
#define RED_OFF    40960               // 2 x 32 fp32
#define LSE_OFF    41216               // 32 fp32
#define SMEM_USED  41344
#define DYN_SMEM   (SMEM_USED + 1024)

// ===================== small projection GEMM (f and g) ======================
__global__ void proj_kernel(const float* __restrict__ X, const float* __restrict__ W,
                            const float* __restrict__ bias, float* __restrict__ Out,
                            int H, int R) {
    __shared__ float Xs[32*33];
    __shared__ float Ws[32*65];
    int r0 = blockIdx.x * 32, j0 = blockIdx.y * 64, b = blockIdx.z;
    int tid = threadIdx.x;
    int r = tid & 31, jg = tid >> 5;
    float acc[8];
#pragma unroll
    for (int i = 0; i < 8; i++) acc[i] = 0.f;
    const float* Xb = X + (size_t)b * H * R;
    for (int h0 = 0; h0 < H; h0 += 32) {
        for (int i = tid; i < 32*32; i += 256) {
            int hh = i >> 5, rr = i & 31;
            Xs[hh*33 + rr] = Xb[(size_t)(h0 + hh) * R + r0 + rr];
        }
        for (int i = tid; i < 64*32; i += 256) {
            int jj = i >> 5, hh = i & 31;
            Ws[hh*65 + jj] = W[(size_t)(j0 + jj) * H + h0 + hh];
        }
        __syncthreads();
#pragma unroll
        for (int hh = 0; hh < 32; hh++) {
            float x = Xs[hh*33 + r];
#pragma unroll
            for (int jj = 0; jj < 8; jj++)
                acc[jj] = fmaf(x, Ws[hh*65 + jg*8 + jj], acc[jj]);
        }
        __syncthreads();
    }
    float* o = Out + ((size_t)b * R + r0 + r) * JH + j0 + jg*8;
#pragma unroll
    for (int jj = 0; jj < 8; jj++) o[jj] = acc[jj] + bias[j0 + jg*8 + jj];
}

// ===================== W_joint fp32 -> bf16 fragment order ==================
__global__ void wconv_kernel(const float* __restrict__ Wj) {
    int i = blockIdx.x * 256 + threadIdx.x;
    if (i >= WFRAG_U32) return;
    int q   = i & 3;
    int u4  = i >> 2;
    int T   = u4 & 31;
    int rest = u4 >> 5;
    int h = rest & 1; rest >>= 1;
    int j = rest & 15;
    int s = rest >> 4;
    int c = s / 10, ks = s - c * 10;
    int v = c * 128 + j * 8 + (T >> 2);
    int k = ks * 64 + (h * 2 + (q >> 1)) * 16 + (q & 1) * 8 + (T & 3) * 2;
    float v0 = 0.f, v1 = 0.f;
    if (v < VC) {
        v0 = Wj[(size_t)v * JH + k];
        v1 = Wj[(size_t)v * JH + k + 1];
    }
    wfrag_dev[i] = pack_bf16x2(v0, v1);
}

// ===================== fused joint GEMM + log_softmax ======================
// CTA = 32 rows, 2 warps, each warp M32 x N64 (Nh=8); 5 CTAs co-resident/SM.
__global__ void __launch_bounds__(NTHREADS, 5)
joint_kernel(const float* __restrict__ b_joint, float* __restrict__ out) {
    extern __shared__ char smraw[];
    uint32_t sm_u = smem_to_u32(smraw);
    uint32_t pad = ((sm_u + 1023) & ~1023u) - sm_u;
    char* sb = smraw + pad;
    uint32_t sb_u = sm_u + pad;

    float* red    = (float*)(sb + RED_OFF);
    float* lse_s  = (float*)(sb + LSE_OFF);
    uint32_t a_base = sb_u + A_OFF;

    int tid  = threadIdx.x;
    int lane = tid & 31, wn = tid >> 5;   // 2 warps: n-halves of each chunk
    int g = lane >> 2, q = lane & 3;

    int bt   = blockIdx.x >> 2;          // (b, t)
    int quar = blockIdx.x & 3;           // which 32-row quarter of U
    int b    = bt >> 8;                  // T = 256
    size_t obase = (size_t)bt * (UU * VC) + (size_t)quar * MROWS * VC;
    const float* grow = g_dev + (size_t)b * UU * JH + (size_t)quar * MROWS * JH;
    const float* frow = f_dev + (size_t)bt * JH;

    // ---- per-warp A ldsm addressing constants ----
    uint32_t rowb[2], r7s[2];
#pragma unroll
    for (int mt = 0; mt < 2; mt++) {
        int row = mt * 16 + (lane & 15);    // local row 0..31
        rowb[mt] = a_base + (uint32_t)(row * 1280);
        r7s[mt]  = (uint32_t)((row & 7) << 4);
    }
    uint32_t hls = (uint32_t)((lane >> 4) << 4);

    // B fragment pointer: warp covers n-octets j = wn*8 + nt (nt 0..7)
    const uint4* __restrict__ wf = ((const uint4*)wfrag_dev) + (uint32_t)(wn * 8 * 64 + lane);

    // ---- build A = relu(f + g) bf16 into swizzled SMEM (32 rows) ----
    for (int i = tid; i < MROWS * 320; i += NTHREADS) {
        int u = i / 320, p = i - u * 320;
        const float2 gv = *(const float2*)(grow + (size_t)u * JH + 2 * p);
        const float2 fv = *(const float2*)(frow + 2 * p);
        float h0 = fmaxf(gv.x + fv.x, 0.f);
        float h1 = fmaxf(gv.y + fv.y, 0.f);
        uint32_t pk = pack_bf16x2(h0, h1);
        int chunk = p >> 2, row = u;
        int sc = (chunk & ~7) | ((chunk & 7) ^ (row & 7));
        *(uint32_t*)(sb + A_OFF + row * 1280 + sc * 16 + (p & 3) * 4) = pk;
    }
    __syncthreads();   // A published

    // ---- main loop: 9 chunks x 20 K32-slices, B double-buffer prefetch ----
    float acc[2][8][4];
    float sums[2][2];
#pragma unroll
    for (int mt = 0; mt < 2; mt++)
#pragma unroll
        for (int h = 0; h < 2; h++) sums[mt][h] = 0.f;

    uint4 bq[2][8];
#pragma unroll
    for (int nt = 0; nt < 8; nt++) bq[0][nt] = wf[nt * 64];

    for (int c = 0; c < NCHUNK; c++) {
#pragma unroll
        for (int mt = 0; mt < 2; mt++)
#pragma unroll
            for (int nt = 0; nt < 8; nt++)
#pragma unroll
                for (int k = 0; k < 4; k++) acc[mt][nt][k] = 0.f;

#pragma unroll 2
        for (int ks = 0; ks < NSLICE; ks++) {
            int s = c * NSLICE + ks;
            int par = ks & 1;
            // prefetch slice s+1 into the other parity (B is (c,k)-indexed: use s)
            if (s + 1 < NSL_TOT) {
                int sn = s + 1;
                const uint4* wsn = wf + (uint32_t)((sn >> 1) * 1024 + (sn & 1) * 32);
#pragma unroll
                for (int nt = 0; nt < 8; nt++) bq[par ^ 1][nt] = wsn[nt * 64];
            }

            // A is k-indexed within the tile: use ks
            uint32_t hi = (uint32_t)((ks >> 1) * 128);
            uint32_t lb = (uint32_t)((ks & 1) << 6) | hls;
#pragma unroll
            for (int kk = 0; kk < 2; kk++) {
                uint32_t lv = lb | (kk << 5);
                uint32_t afr[2][4];
                ldsm_x4(afr[0][0], afr[0][1], afr[0][2], afr[0][3],
                        rowb[0] + hi + (lv ^ r7s[0]));
                ldsm_x4(afr[1][0], afr[1][1], afr[1][2], afr[1][3],
                        rowb[1] + hi + (lv ^ r7s[1]));
#pragma unroll
                for (int nt = 0; nt < 8; nt++) {
                    uint32_t b0 = kk ? bq[par][nt].z : bq[par][nt].x;
                    uint32_t b1 = kk ? bq[par][nt].w : bq[par][nt].y;
                    mma16816(acc[0][nt], afr[0], b0, b1);
                    mma16816(acc[1][nt], afr[1], b0, b1);
                }
            }
        }

        // ---- epilogue: bias from gmem (L1-hot broadcast), scalar logit store,
        //      register exp-sum ----
#pragma unroll
        for (int mt = 0; mt < 2; mt++) {
#pragma unroll
            for (int h = 0; h < 2; h++) {
                int u = mt * 16 + h * 8 + g;
                float* rb = out + obase + (size_t)u * VC;
#pragma unroll
                for (int nt = 0; nt < 8; nt++) {
                    int v = c * NC + wn * 64 + nt * 8 + q * 2;
                    if (v + 1 < VC) {
                        float l0 = acc[mt][nt][h*2 + 0] + __ldg(b_joint + v);
                        float l1 = acc[mt][nt][h*2 + 1] + __ldg(b_joint + v + 1);
                        rb[v] = l0; rb[v + 1] = l1;
                        sums[mt][h] += __expf(l0) + __expf(l1);
                    } else if (v < VC) {
                        float l0 = acc[mt][nt][h*2 + 0] + __ldg(b_joint + v);
                        rb[v] = l0;
                        sums[mt][h] += __expf(l0);
                    }
                }
            }
        }
        __syncthreads();   // convoy only 2 warps of this CTA
    }

    // ---- final per-row logsumexp ----
#pragma unroll
    for (int mt = 0; mt < 2; mt++) {
#pragma unroll
        for (int h = 0; h < 2; h++) {
            float s = sums[mt][h];
            s += __shfl_xor_sync(0xFFFFFFFF, s, 1);
            s += __shfl_xor_sync(0xFFFFFFFF, s, 2);
            if (q == 0) red[wn * MROWS + mt * 16 + h * 8 + g] = s;
        }
    }
    __syncthreads();
    if (tid < MROWS) {
        float s = red[tid] + red[MROWS + tid];
        lse_s[tid] = __logf(s);
    }
    __syncthreads();

    // ---- fixup: subtract lse (region is L2-hot) ----
    for (int u = 0; u < MROWS; u++) {
        float l = lse_s[u];
        float* rb = out + obase + (size_t)u * VC;
        for (int i = tid; i < VC; i += NTHREADS) rb[i] -= l;
    }
}

// ===================== launch ================================
extern "C" void kernel_launch(void* const* d_in, const int* in_sizes, int n_in,
                              void* d_out, int out_size) {
    const float* enc     = (const float*)d_in[0];
    const float* dec     = (const float*)d_in[1];
    const float* W_enc   = (const float*)d_in[2];
    const float* b_enc   = (const float*)d_in[3];
    const float* W_pred  = (const float*)d_in[4];
    const float* b_pred  = (const float*)d_in[5];
    const float* W_joint = (const float*)d_in[6];
    const float* b_joint = (const float*)d_in[7];
    float* out = (float*)d_out;

    cudaFuncSetAttribute(joint_kernel, cudaFuncAttributeMaxDynamicSharedMemorySize, DYN_SMEM);

    float *f_ptr, *g_ptr;
    cudaGetSymbolAddress((void**)&f_ptr, f_dev);
    cudaGetSymbolAddress((void**)&g_ptr, g_dev);

    wconv_kernel<<<(WFRAG_U32 + 255)/256, 256>>>(W_joint);
    proj_kernel<<<dim3(TT/32, JH/64, BB), 256>>>(enc, W_enc, b_enc, f_ptr, ENC_H, TT);
    proj_kernel<<<dim3(UU/32, JH/64, BB), 256>>>(dec, W_pred, b_pred, g_ptr, PRED_H, UU);
    joint_kernel<<<BB*TT*4, NTHREADS, DYN_SMEM>>>(b_joint, out);
}

// round 14
// speedup vs baseline: 1.3063x; 1.3063x over previous
#include <cuda_runtime.h>
#include <cuda_bf16.h>
#include <cstdint>
#include <math.h>

// ===================== problem constants =====================
#define BB 4
#define TT 256
#define UU 128
#define ENC_H 512
#define PRED_H 640
#define JH 640
#define VC 1025            // real classes (1024 GEMM + 1 blank in fixup)
#define VG 1024            // classes via tensor cores
#define NCHUNK 8
#define NC 128             // classes per chunk
#define NSLICE 20          // K slices of 32 per chunk
#define NSL_TOT 160        // total K32 slices
#define NTHREADS 128
#define MROWS 32           // rows per CTA (quarter of a (b,t) tile)
#define WFRAG_U32 (80*16*2*32*4)   // 327680 uint32 = 1.31 MB

// ===================== device scratch ========================
__device__ float f_dev[BB*TT*JH];
__device__ float g_dev[BB*UU*JH];
__device__ uint32_t wfrag_dev[WFRAG_U32];   // W_joint in MMA-fragment order

// ===================== helpers ===========================
__device__ __forceinline__ uint32_t smem_to_u32(const void* p) {
    uint32_t a;
    asm("{ .reg .u64 t; cvta.to.shared.u64 t, %1; cvt.u32.u64 %0, t; }" : "=r"(a) : "l"(p));
    return a;
}
__device__ __forceinline__ uint32_t pack_bf16x2(float lo, float hi) {
    uint32_t p;
    asm("cvt.rn.bf16x2.f32 %0, %1, %2;" : "=r"(p) : "f"(hi), "f"(lo));
    return p;
}
__device__ __forceinline__ void ldsm_x4(uint32_t& r0, uint32_t& r1, uint32_t& r2, uint32_t& r3, uint32_t addr) {
    asm volatile("ldmatrix.sync.aligned.m8n8.x4.shared.b16 {%0,%1,%2,%3}, [%4];"
        : "=r"(r0), "=r"(r1), "=r"(r2), "=r"(r3) : "r"(addr));
}
__device__ __forceinline__ void mma16816(float* d, const uint32_t* a, uint32_t b0, uint32_t b1) {
    asm volatile("mma.sync.aligned.m16n8k16.row.col.f32.bf16.bf16.f32 "
        "{%0,%1,%2,%3}, {%4,%5,%6,%7}, {%8,%9}, {%0,%1,%2,%3};"
        : "+f"(d[0]), "+f"(d[1]), "+f"(d[2]), "+f"(d[3])
        : "r"(a[0]), "r"(a[1]), "r"(a[2]), "r"(a[3]), "r"(b0), "r"(b1));
}

// ===================== SMEM layout (relative to 1KB-aligned base) ==========
#define A_OFF      0                   // 32 x 640 bf16 swizzled: 40960 B
#define BIAS_OFF   40960               // 1025 fp32 (padded to 4224)
#define F_OFF      45184               // 640 fp32
#define RED_OFF    47744               // 4 x 32 fp32
#define LSE_OFF    48256               // 32 fp32
#define BLANK_OFF  48384               // 32 fp32
#define SMEM_USED  48512
#define DYN_SMEM   (SMEM_USED + 1024)

// ===================== small projection GEMM (f and g) ======================
__global__ void proj_kernel(const float* __restrict__ X, const float* __restrict__ W,
                            const float* __restrict__ bias, float* __restrict__ Out,
                            int H, int R) {
    __shared__ float Xs[32*33];
    __shared__ float Ws[32*65];
    int r0 = blockIdx.x * 32, j0 = blockIdx.y * 64, b = blockIdx.z;
    int tid = threadIdx.x;
    int r = tid & 31, jg = tid >> 5;
    float acc[8];
#pragma unroll
    for (int i = 0; i < 8; i++) acc[i] = 0.f;
    const float* Xb = X + (size_t)b * H * R;
    for (int h0 = 0; h0 < H; h0 += 32) {
        for (int i = tid; i < 32*32; i += 256) {
            int hh = i >> 5, rr = i & 31;
            Xs[hh*33 + rr] = Xb[(size_t)(h0 + hh) * R + r0 + rr];
        }
        for (int i = tid; i < 64*32; i += 256) {
            int jj = i >> 5, hh = i & 31;
            Ws[hh*65 + jj] = W[(size_t)(j0 + jj) * H + h0 + hh];
        }
        __syncthreads();
#pragma unroll
        for (int hh = 0; hh < 32; hh++) {
            float x = Xs[hh*33 + r];
#pragma unroll
            for (int jj = 0; jj < 8; jj++)
                acc[jj] = fmaf(x, Ws[hh*65 + jg*8 + jj], acc[jj]);
        }
        __syncthreads();
    }
    float* o = Out + ((size_t)b * R + r0 + r) * JH + j0 + jg*8;
#pragma unroll
    for (int jj = 0; jj < 8; jj++) o[jj] = acc[jj] + bias[j0 + jg*8 + jj];
}

// ===================== W_joint fp32 -> bf16 fragment order ==================
// Covers GEMM classes 0..1023 only (8 chunks); blank handled in fixup.
__global__ void wconv_kernel(const float* __restrict__ Wj) {
    int i = blockIdx.x * 256 + threadIdx.x;
    if (i >= WFRAG_U32) return;
    int q   = i & 3;
    int u4  = i >> 2;
    int T   = u4 & 31;
    int rest = u4 >> 5;
    int h = rest & 1; rest >>= 1;
    int j = rest & 15;
    int s = rest >> 4;             // 0..79
    int c = s / 10, ks = s - c * 10;
    int v = c * 128 + j * 8 + (T >> 2);          // always < 1024
    int k = ks * 64 + (h * 2 + (q >> 1)) * 16 + (q & 1) * 8 + (T & 3) * 2;
    float v0 = Wj[(size_t)v * JH + k];
    float v1 = Wj[(size_t)v * JH + k + 1];
    wfrag_dev[i] = pack_bf16x2(v0, v1);
}

// ===================== fused joint GEMM + log_softmax ======================
// CTA = 32 rows, 4 warps (N32 each); 4 CTAs co-resident per SM.
__global__ void __launch_bounds__(NTHREADS, 4)
joint_kernel(const float* __restrict__ W_joint, const float* __restrict__ b_joint,
             float* __restrict__ out) {
    extern __shared__ char smraw[];
    uint32_t sm_u = smem_to_u32(smraw);
    uint32_t pad = ((sm_u + 1023) & ~1023u) - sm_u;
    char* sb = smraw + pad;
    uint32_t sb_u = sm_u + pad;

    float* bias_s  = (float*)(sb + BIAS_OFF);
    float* f_s     = (float*)(sb + F_OFF);
    float* red     = (float*)(sb + RED_OFF);
    float* lse_s   = (float*)(sb + LSE_OFF);
    float* blank_s = (float*)(sb + BLANK_OFF);
    uint32_t a_base = sb_u + A_OFF;

    int tid  = threadIdx.x;
    int lane = tid & 31, wid = tid >> 5;
    int wn = wid;                        // 1 x 4 warp grid (32 rows, 4 n-quarters)
    int g = lane >> 2, q = lane & 3;

    int bt   = blockIdx.x >> 2;          // (b, t)
    int quar = blockIdx.x & 3;           // which 32-row quarter of U
    int b    = bt >> 8;                  // T = 256
    size_t obase = (size_t)bt * (UU * VC) + (size_t)quar * MROWS * VC;
    const float* grow = g_dev + (size_t)b * UU * JH + (size_t)quar * MROWS * JH;
    const float* frow = f_dev + (size_t)bt * JH;

    // ---- per-warp A ldsm addressing constants ----
    uint32_t rowb[2], r7s[2];
#pragma unroll
    for (int mt = 0; mt < 2; mt++) {
        int row = mt * 16 + (lane & 15);    // local row 0..31
        rowb[mt] = a_base + (uint32_t)(row * 1280);
        r7s[mt]  = (uint32_t)((row & 7) << 4);
    }
    uint32_t hls = (uint32_t)((lane >> 4) << 4);

    // B fragment pointer: per warp covers n-octets j = wn*4 + nt
    const uint4* __restrict__ wf = ((const uint4*)wfrag_dev) + (uint32_t)(wn * 4 * 64 + lane);

    // ---- prologue: bias + f into SMEM ----
    for (int i = tid; i < VC; i += NTHREADS) bias_s[i] = b_joint[i];
    for (int i = tid; i < JH; i += NTHREADS) f_s[i] = frow[i];
    __syncthreads();

    // ---- build A = relu(f + g) bf16 into swizzled SMEM (32 rows) ----
    for (int i = tid; i < MROWS * 320; i += NTHREADS) {
        int u = i / 320, p = i - u * 320;
        const float2 gv = *(const float2*)(grow + (size_t)u * JH + 2 * p);
        float h0 = fmaxf(gv.x + f_s[2*p],     0.f);
        float h1 = fmaxf(gv.y + f_s[2*p + 1], 0.f);
        uint32_t pk = pack_bf16x2(h0, h1);
        int chunk = p >> 2, row = u;
        int sc = (chunk & ~7) | ((chunk & 7) ^ (row & 7));
        *(uint32_t*)(sb + A_OFF + row * 1280 + sc * 16 + (p & 3) * 4) = pk;
    }
    __syncthreads();   // A published

    // ---- main loop: 8 chunks x 20 K32-slices, B double-buffer prefetch ----
    float acc[2][4][4];
    float sums[2][2];
#pragma unroll
    for (int mt = 0; mt < 2; mt++)
#pragma unroll
        for (int h = 0; h < 2; h++) sums[mt][h] = 0.f;

    uint4 bq[2][4];
#pragma unroll
    for (int nt = 0; nt < 4; nt++) bq[0][nt] = wf[nt * 64];

    for (int c = 0; c < NCHUNK; c++) {
#pragma unroll
        for (int mt = 0; mt < 2; mt++)
#pragma unroll
            for (int nt = 0; nt < 4; nt++)
#pragma unroll
                for (int k = 0; k < 4; k++) acc[mt][nt][k] = 0.f;

#pragma unroll 2
        for (int ks = 0; ks < NSLICE; ks++) {
            int s = c * NSLICE + ks;
            int par = ks & 1;
            // prefetch slice s+1 into the other parity (B is (c,k)-indexed: use s)
            if (s + 1 < NSL_TOT) {
                int sn = s + 1;
                const uint4* wsn = wf + (uint32_t)((sn >> 1) * 1024 + (sn & 1) * 32);
#pragma unroll
                for (int nt = 0; nt < 4; nt++) bq[par ^ 1][nt] = wsn[nt * 64];
            }

            // A is k-indexed within the tile: use ks
            uint32_t hi = (uint32_t)((ks >> 1) * 128);
            uint32_t lb = (uint32_t)((ks & 1) << 6) | hls;
#pragma unroll
            for (int kk = 0; kk < 2; kk++) {
                uint32_t lv = lb | (kk << 5);
                uint32_t afr[2][4];
                ldsm_x4(afr[0][0], afr[0][1], afr[0][2], afr[0][3],
                        rowb[0] + hi + (lv ^ r7s[0]));
                ldsm_x4(afr[1][0], afr[1][1], afr[1][2], afr[1][3],
                        rowb[1] + hi + (lv ^ r7s[1]));
#pragma unroll
                for (int nt = 0; nt < 4; nt++) {
                    uint32_t b0 = kk ? bq[par][nt].z : bq[par][nt].x;
                    uint32_t b1 = kk ? bq[par][nt].w : bq[par][nt].y;
                    mma16816(acc[0][nt], afr[0], b0, b1);
                    mma16816(acc[1][nt], afr[1], b0, b1);
                }
            }
        }

        // ---- epilogue: branch-free (all v < 1024 valid) ----
#pragma unroll
        for (int mt = 0; mt < 2; mt++) {
#pragma unroll
            for (int h = 0; h < 2; h++) {
                int u = mt * 16 + h * 8 + g;
                float* rb = out + obase + (size_t)u * VC;
#pragma unroll
                for (int nt = 0; nt < 4; nt++) {
                    int v = c * NC + wn * 32 + nt * 8 + q * 2;
                    float l0 = acc[mt][nt][h*2 + 0] + bias_s[v];
                    float l1 = acc[mt][nt][h*2 + 1] + bias_s[v + 1];
                    rb[v] = l0; rb[v + 1] = l1;
                    sums[mt][h] += __expf(l0) + __expf(l1);
                }
            }
        }
        __syncthreads();   // convoy only 4 warps of this CTA
    }

    // ---- blank class (v = 1024): fp32 dot from resident A SMEM ----
    {
        int row = tid >> 2, part = tid & 3;
        const float2* wb = (const float2*)(W_joint + (size_t)1024 * JH);
        float bsum = 0.f;
#pragma unroll 4
        for (int pp = 0; pp < 80; pp++) {
            int p = part * 80 + pp;
            int chunk = p >> 2;
            int sc = (chunk & ~7) | ((chunk & 7) ^ (row & 7));
            uint32_t pk = *(uint32_t*)(sb + A_OFF + row * 1280 + sc * 16 + (p & 3) * 4);
            float2 av = __bfloat1622float2(*(__nv_bfloat162*)&pk);
            float2 wv = __ldg(wb + p);
            bsum = fmaf(av.x, wv.x, fmaf(av.y, wv.y, bsum));
        }
        bsum += __shfl_xor_sync(0xFFFFFFFF, bsum, 1);
        bsum += __shfl_xor_sync(0xFFFFFFFF, bsum, 2);
        if (part == 0) blank_s[row] = bsum + bias_s[1024];
    }

    // ---- final per-row logsumexp (1024 GEMM classes + blank) ----
#pragma unroll
    for (int mt = 0; mt < 2; mt++) {
#pragma unroll
        for (int h = 0; h < 2; h++) {
            float s = sums[mt][h];
            s += __shfl_xor_sync(0xFFFFFFFF, s, 1);
            s += __shfl_xor_sync(0xFFFFFFFF, s, 2);
            if (q == 0) red[wn * MROWS + mt * 16 + h * 8 + g] = s;
        }
    }
    __syncthreads();
    if (tid < MROWS) {
        float s = red[tid] + red[MROWS + tid] + red[2*MROWS + tid] + red[3*MROWS + tid]
                + __expf(blank_s[tid]);
        lse_s[tid] = __logf(s);
    }
    __syncthreads();

    // ---- fixup: subtract lse; write blank logit (region is L2-hot) ----
    for (int u = 0; u < MROWS; u++) {
        float l = lse_s[u];
        float* rb = out + obase + (size_t)u * VC;
        for (int i = tid; i < VG; i += NTHREADS) rb[i] -= l;
    }
    if (tid < MROWS)
        out[obase + (size_t)tid * VC + 1024] = blank_s[tid] - lse_s[tid];
}

// ===================== launch ================================
extern "C" void kernel_launch(void* const* d_in, const int* in_sizes, int n_in,
                              void* d_out, int out_size) {
    const float* enc     = (const float*)d_in[0];
    const float* dec     = (const float*)d_in[1];
    const float* W_enc   = (const float*)d_in[2];
    const float* b_enc   = (const float*)d_in[3];
    const float* W_pred  = (const float*)d_in[4];
    const float* b_pred  = (const float*)d_in[5];
    const float* W_joint = (const float*)d_in[6];
    const float* b_joint = (const float*)d_in[7];
    float* out = (float*)d_out;

    cudaFuncSetAttribute(joint_kernel, cudaFuncAttributeMaxDynamicSharedMemorySize, DYN_SMEM);

    float *f_ptr, *g_ptr;
    cudaGetSymbolAddress((void**)&f_ptr, f_dev);
    cudaGetSymbolAddress((void**)&g_ptr, g_dev);

    wconv_kernel<<<(WFRAG_U32 + 255)/256, 256>>>(W_joint);
    proj_kernel<<<dim3(TT/32, JH/64, BB), 256>>>(enc, W_enc, b_enc, f_ptr, ENC_H, TT);
    proj_kernel<<<dim3(UU/32, JH/64, BB), 256>>>(dec, W_pred, b_pred, g_ptr, PRED_H, UU);
    joint_kernel<<<BB*TT*4, NTHREADS, DYN_SMEM>>>(W_joint, b_joint, out);
}

// round 15
// speedup vs baseline: 1.5462x; 1.1836x over previous
#include <cuda_runtime.h>
#include <cuda_bf16.h>
#include <cstdint>
#include <math.h>

// ===================== problem constants =====================
#define BB 4
#define TT 256
#define UU 128
#define ENC_H 512
#define PRED_H 640
#define JH 640
#define VC 1025            // real classes (1024 GEMM + 1 blank in fixup)
#define VG 1024            // classes via tensor cores
#define NCHUNK 8
#define NC 128             // classes per chunk
#define NSLICE 20          // K slices of 32 per chunk
#define NSL_TOT 160        // total K32 slices
#define NTHREADS 128
#define MROWS 32           // rows per CTA (quarter of a (b,t) tile)
#define WFRAG_U32 (80*16*2*32*4)   // 327680 uint32 = 1.31 MB

// ===================== device scratch ========================
__device__ float f_dev[BB*TT*JH];
__device__ float g_dev[BB*UU*JH];
__device__ uint32_t wfrag_dev[WFRAG_U32];   // W_joint in MMA-fragment order

// ===================== helpers ===========================
__device__ __forceinline__ uint32_t smem_to_u32(const void* p) {
    uint32_t a;
    asm("{ .reg .u64 t; cvta.to.shared.u64 t, %1; cvt.u32.u64 %0, t; }" : "=r"(a) : "l"(p));
    return a;
}
__device__ __forceinline__ uint32_t pack_bf16x2(float lo, float hi) {
    uint32_t p;
    asm("cvt.rn.bf16x2.f32 %0, %1, %2;" : "=r"(p) : "f"(hi), "f"(lo));
    return p;
}
__device__ __forceinline__ void ldsm_x4(uint32_t& r0, uint32_t& r1, uint32_t& r2, uint32_t& r3, uint32_t addr) {
    asm volatile("ldmatrix.sync.aligned.m8n8.x4.shared.b16 {%0,%1,%2,%3}, [%4];"
        : "=r"(r0), "=r"(r1), "=r"(r2), "=r"(r3) : "r"(addr));
}
__device__ __forceinline__ void mma16816(float* d, const uint32_t* a, uint32_t b0, uint32_t b1) {
    asm volatile("mma.sync.aligned.m16n8k16.row.col.f32.bf16.bf16.f32 "
        "{%0,%1,%2,%3}, {%4,%5,%6,%7}, {%8,%9}, {%0,%1,%2,%3};"
        : "+f"(d[0]), "+f"(d[1]), "+f"(d[2]), "+f"(d[3])
        : "r"(a[0]), "r"(a[1]), "r"(a[2]), "r"(a[3]), "r"(b0), "r"(b1));
}

// ===================== SMEM layout (relative to 1KB-aligned base) ==========
#define A_OFF      0                   // 32 x 640 bf16 swizzled: 40960 B
#define STAGE_OFF  40960               // 32 x 72 fp32 staging: 9216 B
#define BIAS_OFF   50176               // 1025 fp32 (pad to 4224)
#define RED_OFF    54400               // 4 x 32 fp32
#define LSE_OFF    54912               // 32 fp32
#define BLANK_OFF  55040               // 32 fp32
#define SMEM_USED  55168
#define DYN_SMEM   (SMEM_USED + 1024)  // 56192; x4 CTAs = 224768 < 228KB

// ===================== merged prep: proj(f), proj(g), wconv =================
__device__ void proj_body(const float* __restrict__ X, const float* __restrict__ W,
                          const float* __restrict__ bias, float* __restrict__ Out,
                          int H, int R, int rt, int jt, int b,
                          float* Xs, float* Ws) {
    int r0 = rt * 32, j0 = jt * 64;
    int tid = threadIdx.x;
    int r = tid & 31, jg = tid >> 5;
    float acc[8];
#pragma unroll
    for (int i = 0; i < 8; i++) acc[i] = 0.f;
    const float* Xb = X + (size_t)b * H * R;
    for (int h0 = 0; h0 < H; h0 += 32) {
        for (int i = tid; i < 32*32; i += 256) {
            int hh = i >> 5, rr = i & 31;
            Xs[hh*33 + rr] = Xb[(size_t)(h0 + hh) * R + r0 + rr];
        }
        for (int i = tid; i < 64*32; i += 256) {
            int jj = i >> 5, hh = i & 31;
            Ws[hh*65 + jj] = W[(size_t)(j0 + jj) * H + h0 + hh];
        }
        __syncthreads();
#pragma unroll
        for (int hh = 0; hh < 32; hh++) {
            float x = Xs[hh*33 + r];
#pragma unroll
            for (int jj = 0; jj < 8; jj++)
                acc[jj] = fmaf(x, Ws[hh*65 + jg*8 + jj], acc[jj]);
        }
        __syncthreads();
    }
    float* o = Out + ((size_t)b * R + r0 + r) * JH + j0 + jg*8;
#pragma unroll
    for (int jj = 0; jj < 8; jj++) o[jj] = acc[jj] + bias[j0 + jg*8 + jj];
}

__global__ void prep_kernel(const float* __restrict__ enc, const float* __restrict__ W_enc,
                            const float* __restrict__ b_enc,
                            const float* __restrict__ dec, const float* __restrict__ W_pred,
                            const float* __restrict__ b_pred,
                            const float* __restrict__ Wj,
                            float* __restrict__ f_out, float* __restrict__ g_out) {
    __shared__ float Xs[32*33];
    __shared__ float Ws[32*65];
    int bx = blockIdx.x;
    if (bx < 320) {                                   // proj f: 8 x 10 x 4
        int rt = bx & 7, jt = (bx >> 3) % 10, b = bx / 80;
        proj_body(enc, W_enc, b_enc, f_out, ENC_H, TT, rt, jt, b, Xs, Ws);
    } else if (bx < 480) {                            // proj g: 4 x 10 x 4
        int pb = bx - 320;
        int rt = pb & 3, jt = (pb >> 2) % 10, b = pb / 40;
        proj_body(dec, W_pred, b_pred, g_out, PRED_H, UU, rt, jt, b, Xs, Ws);
    } else {                                          // wconv: 1280 blocks
        int i = (bx - 480) * 256 + threadIdx.x;
        if (i < WFRAG_U32) {
            int q   = i & 3;
            int u4  = i >> 2;
            int T   = u4 & 31;
            int rest = u4 >> 5;
            int h = rest & 1; rest >>= 1;
            int j = rest & 15;
            int s = rest >> 4;             // 0..79
            int c = s / 10, ks = s - c * 10;
            int v = c * 128 + j * 8 + (T >> 2);          // always < 1024
            int k = ks * 64 + (h * 2 + (q >> 1)) * 16 + (q & 1) * 8 + (T & 3) * 2;
            float v0 = Wj[(size_t)v * JH + k];
            float v1 = Wj[(size_t)v * JH + k + 1];
            wfrag_dev[i] = pack_bf16x2(v0, v1);
        }
    }
}

// ===================== fused joint GEMM + log_softmax ======================
// CTA = 32 rows, 4 warps (N32 each, octets {wn,wn+4,wn+8,wn+12}); 4 CTAs/SM.
__global__ void __launch_bounds__(NTHREADS, 4)
joint_kernel(const float* __restrict__ W_joint, const float* __restrict__ b_joint,
             float* __restrict__ out) {
    extern __shared__ char smraw[];
    uint32_t sm_u = smem_to_u32(smraw);
    uint32_t pad = ((sm_u + 1023) & ~1023u) - sm_u;
    char* sb = smraw + pad;
    uint32_t sb_u = sm_u + pad;

    float* stage   = (float*)(sb + STAGE_OFF);
    float* bias_s  = (float*)(sb + BIAS_OFF);
    float* red     = (float*)(sb + RED_OFF);
    float* lse_s   = (float*)(sb + LSE_OFF);
    float* blank_s = (float*)(sb + BLANK_OFF);
    uint32_t a_base = sb_u + A_OFF;

    int tid  = threadIdx.x;
    int lane = tid & 31, wid = tid >> 5;
    int wn = wid;                        // warp owns octets wn + 4*nt
    int g = lane >> 2, q = lane & 3;

    int bt   = blockIdx.x >> 2;          // (b, t)
    int quar = blockIdx.x & 3;           // which 32-row quarter of U
    int b    = bt >> 8;                  // T = 256
    size_t obase = (size_t)bt * (UU * VC) + (size_t)quar * MROWS * VC;
    const float* grow = g_dev + (size_t)b * UU * JH + (size_t)quar * MROWS * JH;
    const float* frow = f_dev + (size_t)bt * JH;

    // ---- per-warp A ldsm addressing constants ----
    uint32_t rowb[2], r7s[2];
#pragma unroll
    for (int mt = 0; mt < 2; mt++) {
        int row = mt * 16 + (lane & 15);    // local row 0..31
        rowb[mt] = a_base + (uint32_t)(row * 1280);
        r7s[mt]  = (uint32_t)((row & 7) << 4);
    }
    uint32_t hls = (uint32_t)((lane >> 4) << 4);

    // B fragment pointer: octet stride in wfrag is 64 uint4; warp base octet = wn
    const uint4* __restrict__ wf = ((const uint4*)wfrag_dev) + (uint32_t)(wn * 64 + lane);

    // ---- prologue: bias into SMEM ----
    for (int i = tid; i < VC; i += NTHREADS) bias_s[i] = b_joint[i];

    // ---- build A = relu(f + g) bf16 into swizzled SMEM (32 rows) ----
    for (int i = tid; i < MROWS * 320; i += NTHREADS) {
        int u = i / 320, p = i - u * 320;
        const float2 gv = *(const float2*)(grow + (size_t)u * JH + 2 * p);
        const float2 fv = *(const float2*)(frow + 2 * p);
        float h0 = fmaxf(gv.x + fv.x, 0.f);
        float h1 = fmaxf(gv.y + fv.y, 0.f);
        uint32_t pk = pack_bf16x2(h0, h1);
        int chunk = p >> 2, row = u;
        int sc = (chunk & ~7) | ((chunk & 7) ^ (row & 7));
        *(uint32_t*)(sb + A_OFF + row * 1280 + sc * 16 + (p & 3) * 4) = pk;
    }
    __syncthreads();   // A + bias published

    // ---- main loop: 8 chunks x 20 K32-slices, B double-buffer prefetch ----
    float acc[2][4][4];
    float sums[2][2];
#pragma unroll
    for (int mt = 0; mt < 2; mt++)
#pragma unroll
        for (int h = 0; h < 2; h++) sums[mt][h] = 0.f;

    uint4 bq[2][4];
#pragma unroll
    for (int nt = 0; nt < 4; nt++) bq[0][nt] = wf[nt * 256];

    for (int c = 0; c < NCHUNK; c++) {
#pragma unroll
        for (int mt = 0; mt < 2; mt++)
#pragma unroll
            for (int nt = 0; nt < 4; nt++)
#pragma unroll
                for (int k = 0; k < 4; k++) acc[mt][nt][k] = 0.f;

#pragma unroll 2
        for (int ks = 0; ks < NSLICE; ks++) {
            int s = c * NSLICE + ks;
            int par = ks & 1;
            // prefetch slice s+1 into the other parity (B is (c,k)-indexed: use s)
            if (s + 1 < NSL_TOT) {
                int sn = s + 1;
                const uint4* wsn = wf + (uint32_t)((sn >> 1) * 1024 + (sn & 1) * 32);
#pragma unroll
                for (int nt = 0; nt < 4; nt++) bq[par ^ 1][nt] = wsn[nt * 256];
            }

            // A is k-indexed within the tile: use ks
            uint32_t hi = (uint32_t)((ks >> 1) * 128);
            uint32_t lb = (uint32_t)((ks & 1) << 6) | hls;
#pragma unroll
            for (int kk = 0; kk < 2; kk++) {
                uint32_t lv = lb | (kk << 5);
                uint32_t afr[2][4];
                ldsm_x4(afr[0][0], afr[0][1], afr[0][2], afr[0][3],
                        rowb[0] + hi + (lv ^ r7s[0]));
                ldsm_x4(afr[1][0], afr[1][1], afr[1][2], afr[1][3],
                        rowb[1] + hi + (lv ^ r7s[1]));
#pragma unroll
                for (int nt = 0; nt < 4; nt++) {
                    uint32_t b0 = kk ? bq[par][nt].z : bq[par][nt].x;
                    uint32_t b1 = kk ? bq[par][nt].w : bq[par][nt].y;
                    mma16816(acc[0][nt], afr[0], b0, b1);
                    mma16816(acc[1][nt], afr[1], b0, b1);
                }
            }
        }

        // ---- staged epilogue: two 64-col halves through SMEM ----
#pragma unroll
        for (int half = 0; half < 2; half++) {
            // STS fragments of this half (nt = half*2 + {0,1})
#pragma unroll
            for (int mt = 0; mt < 2; mt++) {
#pragma unroll
                for (int h = 0; h < 2; h++) {
                    int row = mt * 16 + h * 8 + g;
#pragma unroll
                    for (int nti = 0; nti < 2; nti++) {
                        int nt = half * 2 + nti;
                        int v = c * NC + (wn + nt * 4) * 8 + q * 2;
                        float l0 = acc[mt][nt][h*2 + 0] + bias_s[v];
                        float l1 = acc[mt][nt][h*2 + 1] + bias_s[v + 1];
                        sums[mt][h] += __expf(l0) + __expf(l1);
                        int col = wn * 8 + nti * 32 + q * 2;   // local col in half
                        *(float2*)(stage + row * 72 + col) = make_float2(l0, l1);
                    }
                }
            }
            __syncthreads();
            // coalesced copy-out: warp wid handles rows wid*8..wid*8+7
            {
                size_t cb = obase + (size_t)(c * NC + half * 64);
#pragma unroll
                for (int r = 0; r < 8; r++) {
                    int row = wid * 8 + r;
#pragma unroll
                    for (int seg = 0; seg < 2; seg++) {
                        float val = stage[row * 72 + seg * 32 + lane];
                        out[cb + (size_t)row * VC + seg * 32 + lane] = val;
                    }
                }
            }
            __syncthreads();
        }
    }

    // ---- blank class (v = 1024): fp32 dot from resident A SMEM ----
    {
        int row = tid >> 2, part = tid & 3;
        const float2* wb = (const float2*)(W_joint + (size_t)1024 * JH);
        float bsum = 0.f;
#pragma unroll 4
        for (int pp = 0; pp < 80; pp++) {
            int p = part * 80 + pp;
            int chunk = p >> 2;
            int sc = (chunk & ~7) | ((chunk & 7) ^ (row & 7));
            uint32_t pk = *(uint32_t*)(sb + A_OFF + row * 1280 + sc * 16 + (p & 3) * 4);
            float2 av = __bfloat1622float2(*(__nv_bfloat162*)&pk);
            float2 wv = __ldg(wb + p);
            bsum = fmaf(av.x, wv.x, fmaf(av.y, wv.y, bsum));
        }
        bsum += __shfl_xor_sync(0xFFFFFFFF, bsum, 1);
        bsum += __shfl_xor_sync(0xFFFFFFFF, bsum, 2);
        if (part == 0) blank_s[row] = bsum + bias_s[1024];
    }

    // ---- final per-row logsumexp (1024 GEMM classes + blank) ----
#pragma unroll
    for (int mt = 0; mt < 2; mt++) {
#pragma unroll
        for (int h = 0; h < 2; h++) {
            float s = sums[mt][h];
            s += __shfl_xor_sync(0xFFFFFFFF, s, 1);
            s += __shfl_xor_sync(0xFFFFFFFF, s, 2);
            if (q == 0) red[wn * MROWS + mt * 16 + h * 8 + g] = s;
        }
    }
    __syncthreads();
    if (tid < MROWS) {
        float s = red[tid] + red[MROWS + tid] + red[2*MROWS + tid] + red[3*MROWS + tid]
                + __expf(blank_s[tid]);
        lse_s[tid] = __logf(s);
    }
    __syncthreads();

    // ---- fixup: subtract lse with aligned float4 over row interior ----
    for (int u = 0; u < MROWS; u++) {
        float l = lse_s[u];
        size_t a = obase + (size_t)u * VC;
        float* rb = out + a;
        int a0 = (4 - (int)(a & 3)) & 3;
        int n4 = (VG - a0) >> 2;
        float4* rb4 = (float4*)(rb + a0);
        for (int i = tid; i < n4; i += NTHREADS) {
            float4 v = rb4[i];
            v.x -= l; v.y -= l; v.z -= l; v.w -= l;
            rb4[i] = v;
        }
        if (tid < a0) rb[tid] -= l;
        int tail0 = a0 + (n4 << 2);
        if (tid < VG - tail0) rb[tail0 + tid] -= l;
    }
    if (tid < MROWS)
        out[obase + (size_t)tid * VC + 1024] = blank_s[tid] - lse_s[tid];
}

// ===================== launch ================================
extern "C" void kernel_launch(void* const* d_in, const int* in_sizes, int n_in,
                              void* d_out, int out_size) {
    const float* enc     = (const float*)d_in[0];
    const float* dec     = (const float*)d_in[1];
    const float* W_enc   = (const float*)d_in[2];
    const float* b_enc   = (const float*)d_in[3];
    const float* W_pred  = (const float*)d_in[4];
    const float* b_pred  = (const float*)d_in[5];
    const float* W_joint = (const float*)d_in[6];
    const float* b_joint = (const float*)d_in[7];
    float* out = (float*)d_out;

    cudaFuncSetAttribute(joint_kernel, cudaFuncAttributeMaxDynamicSharedMemorySize, DYN_SMEM);

    float *f_ptr, *g_ptr;
    cudaGetSymbolAddress((void**)&f_ptr, f_dev);
    cudaGetSymbolAddress((void**)&g_ptr, g_dev);

    prep_kernel<<<480 + WFRAG_U32/256, 256>>>(enc, W_enc, b_enc,
                                              dec, W_pred, b_pred,
                                              W_joint, f_ptr, g_ptr);
    joint_kernel<<<BB*TT*4, NTHREADS, DYN_SMEM>>>(W_joint, b_joint, out);
}